// round 10
// baseline (speedup 1.0000x reference)
#include <cuda_runtime.h>
#include <cuda_fp16.h>
#include <cstdint>
#include <math.h>

// Problem constants (B=1, DIM=512, T=8, H=64, W=64)
#define MDIM 512
#define KDIM 512
#define NDIM 32768
#define SQRT_C 22.62741699796952f

// ---------------- main GEMM tiling (128x64, 3 CTAs/SM) ----------------
#define BM 128
#define BN 64
#define BK 32
#define NITER (KDIM / BK)      // 16
#define STAGES 4
#define AROW_H 40              // A padded row (halves) -> 80B
#define BROW_H 72              // B padded row (halves) -> 144B (banks 4r mod 32: conflict-free)
#define A_BYTES (BM * AROW_H * 2)      // 10240
#define B_BYTES (BK * BROW_H * 2)      // 4608
#define STAGE_B (A_BYTES + B_BYTES)    // 14848
#define SMEM_TOTAL (STAGES * STAGE_B)  // 59392

// ---------------- fuse-weights GEMM tiling (R7 proven) ----------------
#define FW_AROW_H 40
#define FW_BROW_H 136
#define FW_A_BYTES (128 * FW_AROW_H * 2)   // 10240
#define FW_B_BYTES (32 * FW_BROW_H * 2)    // 8704
#define FW_STAGE_B (FW_A_BYTES + FW_B_BYTES)  // 18944
#define FW_SMEM (5 * FW_STAGE_B)              // 94720

// ---------------- scratch ----------------
__device__ __half g_Wf[MDIM * KDIM];      // fused weight, fp16
__device__ __half g_xh[KDIM * NDIM];      // x converted to fp16
__device__ __half g_wph[MDIM * KDIM];     // w_proj fp16
__device__ __half g_wvh[MDIM * KDIM];     // (W_v * gamma) fp16
__device__ float  g_bias[MDIM];
__device__ float  g_s[NDIM];

// ---------------- helpers ----------------
__device__ __forceinline__ uint32_t smem_u32(const void* p) {
    uint32_t a;
    asm("{ .reg .u64 t; cvta.to.shared.u64 t, %1; cvt.u32.u64 %0, t; }" : "=r"(a) : "l"(p));
    return a;
}
__device__ __forceinline__ void cp_async16(uint32_t dst, const void* src) {
    asm volatile("cp.async.cg.shared.global [%0], [%1], 16;" :: "r"(dst), "l"(src) : "memory");
}
#define LDSM_X4(r0, r1, r2, r3, addr)                                         \
    asm volatile("ldmatrix.sync.aligned.m8n8.x4.shared.b16 {%0,%1,%2,%3}, [%4];" \
        : "=r"(r0), "=r"(r1), "=r"(r2), "=r"(r3) : "r"(addr))
#define LDSM_X4_T(r0, r1, r2, r3, addr)                                       \
    asm volatile("ldmatrix.sync.aligned.m8n8.x4.trans.shared.b16 {%0,%1,%2,%3}, [%4];" \
        : "=r"(r0), "=r"(r1), "=r"(r2), "=r"(r3) : "r"(addr))

__device__ __forceinline__ void mma_f16(float c[4], uint32_t a0, uint32_t a1, uint32_t a2, uint32_t a3,
                                        uint32_t b0, uint32_t b1) {
    asm volatile(
        "mma.sync.aligned.m16n8k16.row.col.f32.f16.f16.f32 "
        "{%0,%1,%2,%3}, {%4,%5,%6,%7}, {%8,%9}, {%0,%1,%2,%3};"
        : "+f"(c[0]), "+f"(c[1]), "+f"(c[2]), "+f"(c[3])
        : "r"(a0), "r"(a1), "r"(a2), "r"(a3), "r"(b0), "r"(b1));
}

// ---------------- kernel 1: prep (converts + bias, blockIdx-dispatched) ----------------
__global__ __launch_bounds__(256) void prep_kernel(
    const float* __restrict__ w_proj, const float* __restrict__ w_qkv,
    const float* __restrict__ gamma,  const float* __restrict__ b_qkv,
    const float* __restrict__ b_proj,
    __half* __restrict__ wph, __half* __restrict__ wvh, float* __restrict__ bias)
{
    const int bx  = blockIdx.x;
    const int tid = threadIdx.x;
    if (bx < 256) {
        const int i = (bx * 256 + tid) * 4;
        float4 v = *reinterpret_cast<const float4*>(w_proj + i);
        *reinterpret_cast<__half2*>(wph + i)     = __floats2half2_rn(v.x, v.y);
        *reinterpret_cast<__half2*>(wph + i + 2) = __floats2half2_rn(v.z, v.w);
    } else if (bx < 512) {
        const float* in = w_qkv + (size_t)1024 * KDIM;
        const int i = ((bx - 256) * 256 + tid) * 4;
        const int c = i & (KDIM - 1);
        float4 g = *reinterpret_cast<const float4*>(gamma + c);
        float4 v = *reinterpret_cast<const float4*>(in + i);
        *reinterpret_cast<__half2*>(wvh + i)     = __floats2half2_rn(v.x * g.x, v.y * g.y);
        *reinterpret_cast<__half2*>(wvh + i + 2) = __floats2half2_rn(v.z * g.z, v.w * g.w);
    } else {
        const int lane = tid & 31;
        const int o    = (bx - 512) * 8 + (tid >> 5);
        const float* wp = w_proj + (size_t)o * KDIM;
        const float* bq = b_qkv + 1024;
        float acc = 0.f;
        #pragma unroll
        for (int i = 0; i < 16; i++) {
            const int k = lane + 32 * i;
            acc = fmaf(wp[k], bq[k], acc);
        }
        #pragma unroll
        for (int off = 16; off > 0; off >>= 1)
            acc += __shfl_xor_sync(0xFFFFFFFFu, acc, off);
        if (lane == 0) bias[o] = acc + b_proj[o];
    }
}

// ---------------- kernel 2: scale (blocks 0..255) + fuse-weights mma (blocks 256..271) ----------------
__global__ __launch_bounds__(256, 2) void scale_fw_kernel(
    const float* __restrict__ x, float* __restrict__ s, __half* __restrict__ xh,
    const __half* __restrict__ Awp, const __half* __restrict__ Bwv,
    __half* __restrict__ Wf)
{
    extern __shared__ char smem[];
    const int tid = threadIdx.x;

    if (blockIdx.x < 256) {
        // ---- RMS scale + fp16 conversion, 128 tokens per block ----
        float2* red = reinterpret_cast<float2*>(smem);
        const int nl = tid & 63;
        const int q  = tid >> 6;
        const int n  = blockIdx.x * 128 + nl * 2;

        const float2* p = reinterpret_cast<const float2*>(x + (size_t)(q * 128) * NDIM + n);
        __half2* ph = reinterpret_cast<__half2*>(xh + (size_t)(q * 128) * NDIM + n);
        float ax = 0.f, ay = 0.f;
        #pragma unroll 8
        for (int c = 0; c < 128; c++) {
            float2 v = p[(size_t)c * (NDIM / 2)];
            ax = fmaf(v.x, v.x, ax);
            ay = fmaf(v.y, v.y, ay);
            ph[(size_t)c * (NDIM / 2)] = __floats2half2_rn(v.x, v.y);
        }
        red[tid] = make_float2(ax, ay);
        __syncthreads();
        if (tid < 64) {
            float2 a = red[tid], b = red[tid + 64], c2 = red[tid + 128], d = red[tid + 192];
            float tx2 = a.x + b.x + c2.x + d.x;
            float ty2 = a.y + b.y + c2.y + d.y;
            float2 sv;
            sv.x = SQRT_C / fmaxf(sqrtf(tx2), 1e-12f);
            sv.y = SQRT_C / fmaxf(sqrtf(ty2), 1e-12f);
            *reinterpret_cast<float2*>(s + blockIdx.x * 128 + tid * 2) = sv;
        }
        return;
    }

    // ---- fuse-weights GEMM: Wf = wph @ wvh  (B stride 512, 128x128 tiles) ----
    const uint32_t sbase = smem_u32(smem);
    const int bxx  = blockIdx.x - 256;
    const int lane = tid & 31;
    const int wid  = tid >> 5;
    const int wm   = wid >> 2;
    const int wn   = wid & 3;
    const int ty   = lane >> 2;
    const int tx   = lane & 3;
    const int m0   = (bxx >> 2) * 128;
    const int n0   = (bxx & 3) * 128;

    const int a_row = tid >> 1;
    const int a_sp  = (tid & 1) * 2;
    const int b_row = tid >> 3;
    const int b_sp  = (tid & 7) * 2;
    const __half* a_src = Awp + (size_t)(m0 + a_row) * KDIM + a_sp * 8;
    const __half* b_src = Bwv + (size_t)b_row * 512 + n0 + b_sp * 8;

    float c[4][4][4] = {};

    auto issue = [&](int ck) {
        const uint32_t ab = sbase + (uint32_t)(ck % 5) * FW_STAGE_B;
        const uint32_t bb = ab + FW_A_BYTES;
        const int k0 = ck * BK;
        #pragma unroll
        for (int ss = 0; ss < 2; ss++)
            cp_async16(ab + (uint32_t)(a_row * 80 + (a_sp + ss) * 16), a_src + k0 + ss * 8);
        #pragma unroll
        for (int ss = 0; ss < 2; ss++)
            cp_async16(bb + (uint32_t)(b_row * 272 + (b_sp + ss) * 16),
                       b_src + (size_t)k0 * 512 + ss * 8);
        asm volatile("cp.async.commit_group;" ::: "memory");
    };

    issue(0); issue(1); issue(2); issue(3);

    const uint32_t a_lm = (uint32_t)(((wm * 64 + (lane & 15)) * FW_AROW_H + (lane >> 4) * 8) * 2);
    const uint32_t b_lm = (uint32_t)(FW_A_BYTES + (((lane & 15)) * FW_BROW_H + wn * 32 + (lane >> 4) * 8) * 2);

    #pragma unroll 1
    for (int it = 0; it < NITER; ++it) {
        if (it + 3 < NITER)      asm volatile("cp.async.wait_group 3;" ::: "memory");
        else if (it + 2 < NITER) asm volatile("cp.async.wait_group 2;" ::: "memory");
        else if (it + 1 < NITER) asm volatile("cp.async.wait_group 1;" ::: "memory");
        else                     asm volatile("cp.async.wait_group 0;" ::: "memory");
        __syncthreads();
        if (it + 4 < NITER) issue(it + 4);

        const uint32_t stb = sbase + (uint32_t)(it % 5) * FW_STAGE_B;
        #pragma unroll
        for (int kk = 0; kk < 2; kk++) {
            uint32_t a[4][4];
            #pragma unroll
            for (int mt = 0; mt < 4; mt++)
                LDSM_X4(a[mt][0], a[mt][1], a[mt][2], a[mt][3],
                        stb + a_lm + mt * (16 * FW_AROW_H * 2) + kk * 32);
            uint32_t b[4][2];
            #pragma unroll
            for (int ntp = 0; ntp < 2; ntp++)
                LDSM_X4_T(b[ntp * 2][0], b[ntp * 2][1], b[ntp * 2 + 1][0], b[ntp * 2 + 1][1],
                          stb + b_lm + kk * (16 * FW_BROW_H * 2) + ntp * 32);
            #pragma unroll
            for (int mt = 0; mt < 4; mt++)
                #pragma unroll
                for (int nt = 0; nt < 4; nt++)
                    mma_f16(c[mt][nt], a[mt][0], a[mt][1], a[mt][2], a[mt][3],
                            b[nt][0], b[nt][1]);
        }
    }

    #pragma unroll
    for (int mt = 0; mt < 4; mt++)
        #pragma unroll
        for (int h = 0; h < 2; h++) {
            const int m = m0 + wm * 64 + mt * 16 + ty + h * 8;
            #pragma unroll
            for (int nt = 0; nt < 4; nt++) {
                const int nc = wn * 32 + nt * 8 + 2 * tx;
                *reinterpret_cast<__half2*>(Wf + (size_t)m * KDIM + n0 + nc) =
                    __floats2half2_rn(c[mt][nt][h * 2 + 0], c[mt][nt][h * 2 + 1]);
            }
        }
}

// ================= kernel 3: main GEMM (128x64 tiles, 3 CTAs/SM) =================
// grid (4 m-tiles fastest, 512 n-tiles). 8 warps = 2m x 4n, warp tile 64x16.
__global__ __launch_bounds__(256, 3) void main_gemm_kernel(
    const __half* __restrict__ A,    // Wf [512,512] fp16
    const __half* __restrict__ Bh,   // x_h [512,32768] fp16 (operand + residual)
    const float* __restrict__ s,
    const float* __restrict__ bias,
    float* __restrict__ C)
{
    extern __shared__ char smem[];
    const uint32_t sbase = smem_u32(smem);
    const int tid  = threadIdx.x;
    const int lane = tid & 31;
    const int wid  = tid >> 5;
    const int wm   = wid >> 2;          // 0..1
    const int wn   = wid & 3;           // 0..3 (n-blocks of 16)
    const int ty   = lane >> 2;
    const int tx   = lane & 3;
    const int m0   = blockIdx.x * BM;   // 4 m-tiles, fastest
    const int n0   = blockIdx.y * BN;   // 512 n-tiles

    // loaders: A 128 rows x 64B (4 segs, 2/thread); B 32 rows x 128B (8 segs, 1/thread)
    const int a_row = tid >> 1;
    const int a_sp  = (tid & 1) * 2;
    const int b_row = tid >> 3;
    const int b_seg = tid & 7;
    const __half* a_src = A + (size_t)(m0 + a_row) * KDIM + a_sp * 8;
    const __half* b_src = Bh + (size_t)b_row * NDIM + n0 + b_seg * 8;

    float c[4][2][4] = {};

    auto issue = [&](int ck) {
        const uint32_t ab = sbase + (uint32_t)(ck % STAGES) * STAGE_B;
        const uint32_t bb = ab + A_BYTES;
        const int k0 = ck * BK;
        #pragma unroll
        for (int ss = 0; ss < 2; ss++)
            cp_async16(ab + (uint32_t)(a_row * 80 + (a_sp + ss) * 16), a_src + k0 + ss * 8);
        cp_async16(bb + (uint32_t)(b_row * 144 + b_seg * 16),
                   b_src + (size_t)k0 * NDIM);
        asm volatile("cp.async.commit_group;" ::: "memory");
    };

    issue(0); issue(1); issue(2);

    const uint32_t a_lm = (uint32_t)(((wm * 64 + (lane & 15)) * AROW_H + (lane >> 4) * 8) * 2);
    const uint32_t b_lm = (uint32_t)(A_BYTES + (((lane & 15)) * BROW_H + wn * 16 + (lane >> 4) * 8) * 2);

    #pragma unroll 1
    for (int it = 0; it < NITER; ++it) {
        if (it + 2 < NITER)      asm volatile("cp.async.wait_group 2;" ::: "memory");
        else if (it + 1 < NITER) asm volatile("cp.async.wait_group 1;" ::: "memory");
        else                     asm volatile("cp.async.wait_group 0;" ::: "memory");
        __syncthreads();
        if (it + 3 < NITER) issue(it + 3);

        const uint32_t stb = sbase + (uint32_t)(it % STAGES) * STAGE_B;
        #pragma unroll
        for (int kk = 0; kk < 2; kk++) {
            uint32_t a[4][4];
            #pragma unroll
            for (int mt = 0; mt < 4; mt++)
                LDSM_X4(a[mt][0], a[mt][1], a[mt][2], a[mt][3],
                        stb + a_lm + mt * (16 * AROW_H * 2) + kk * 32);
            uint32_t b[2][2];
            LDSM_X4_T(b[0][0], b[0][1], b[1][0], b[1][1],
                      stb + b_lm + kk * (16 * BROW_H * 2));
            #pragma unroll
            for (int mt = 0; mt < 4; mt++)
                #pragma unroll
                for (int nt = 0; nt < 2; nt++)
                    mma_f16(c[mt][nt], a[mt][0], a[mt][1], a[mt][2], a[mt][3],
                            b[nt][0], b[nt][1]);
        }
    }

    // ---- epilogue: out = D*s[n] + bias[m] + xh[m][n] ----
    #pragma unroll
    for (int mt = 0; mt < 4; mt++) {
        #pragma unroll
        for (int h = 0; h < 2; h++) {
            const int m = m0 + wm * 64 + mt * 16 + ty + h * 8;
            const float bm = bias[m];
            const __half2* xrow = reinterpret_cast<const __half2*>(Bh + (size_t)m * NDIM + n0);
            float* crow = C + (size_t)m * NDIM + n0;
            #pragma unroll
            for (int nt = 0; nt < 2; nt++) {
                const int nc = wn * 16 + nt * 8 + 2 * tx;
                float2 xv = __half22float2(xrow[nc >> 1]);
                float2 sv = *reinterpret_cast<const float2*>(s + n0 + nc);
                float2 ov;
                ov.x = fmaf(c[mt][nt][h * 2 + 0], sv.x, bm + xv.x);
                ov.y = fmaf(c[mt][nt][h * 2 + 1], sv.y, bm + xv.y);
                *reinterpret_cast<float2*>(crow + nc) = ov;
            }
        }
    }
}

// ---------------- launcher ----------------
extern "C" void kernel_launch(void* const* d_in, const int* in_sizes, int n_in,
                              void* d_out, int out_size)
{
    const float* x      = (const float*)d_in[0];
    const float* gamma  = (const float*)d_in[1];
    const float* w_qkv  = (const float*)d_in[2];
    const float* b_qkv  = (const float*)d_in[3];
    const float* w_proj = (const float*)d_in[4];
    const float* b_proj = (const float*)d_in[5];
    float* out = (float*)d_out;

    __half *Wf, *xh, *wph, *wvh;
    float *bias, *s;
    cudaGetSymbolAddress((void**)&Wf,   g_Wf);
    cudaGetSymbolAddress((void**)&xh,   g_xh);
    cudaGetSymbolAddress((void**)&wph,  g_wph);
    cudaGetSymbolAddress((void**)&wvh,  g_wvh);
    cudaGetSymbolAddress((void**)&bias, g_bias);
    cudaGetSymbolAddress((void**)&s,    g_s);

    cudaFuncSetAttribute(scale_fw_kernel,
                         cudaFuncAttributeMaxDynamicSharedMemorySize, FW_SMEM);
    cudaFuncSetAttribute(main_gemm_kernel,
                         cudaFuncAttributeMaxDynamicSharedMemorySize, SMEM_TOTAL);

    prep_kernel<<<576, 256>>>(w_proj, w_qkv, gamma, b_qkv, b_proj, wph, wvh, bias);
    scale_fw_kernel<<<272, 256, FW_SMEM>>>(x, s, xh, wph, wvh, Wf);

    dim3 grid(MDIM / BM, NDIM / BN);   // (4, 512): m fastest
    main_gemm_kernel<<<grid, 256, SMEM_TOTAL>>>(Wf, xh, s, bias, out);
}

// round 11
// speedup vs baseline: 1.0319x; 1.0319x over previous
#include <cuda_runtime.h>
#include <cuda_fp16.h>
#include <cstdint>
#include <math.h>

// Problem constants (B=1, DIM=512, T=8, H=64, W=64)
#define MDIM 512
#define KDIM 512
#define NDIM 32768
#define SQRT_C 22.62741699796952f

// ---------------- main GEMM tiling (128x128, BK=64, 3 stages, 2 CTAs/SM) ----------------
#define BM 128
#define BN 128
#define BK 64
#define NITER (KDIM / BK)      // 8
#define STAGES 3
#define AROW_H 72              // A padded row (halves) -> 144B (banks 4r mod 32: conflict-free)
#define BROW_H 136             // B padded row (halves) -> 272B
#define A_BYTES (BM * AROW_H * 2)      // 18432
#define B_BYTES (BK * BROW_H * 2)      // 17408
#define STAGE_B (A_BYTES + B_BYTES)    // 35840
#define SMEM_TOTAL (STAGES * STAGE_B)  // 107520

// ---------------- fuse-weights GEMM tiling (R7 proven, BK=32) ----------------
#define FW_BK 32
#define FW_NITER 16
#define FW_AROW_H 40
#define FW_BROW_H 136
#define FW_A_BYTES (128 * FW_AROW_H * 2)   // 10240
#define FW_B_BYTES (32 * FW_BROW_H * 2)    // 8704
#define FW_STAGE_B (FW_A_BYTES + FW_B_BYTES)  // 18944
#define FW_SMEM (5 * FW_STAGE_B)              // 94720

// ---------------- scratch ----------------
__device__ __half g_Wf[MDIM * KDIM];      // fused weight, fp16
__device__ __half g_xh[KDIM * NDIM];      // x converted to fp16
__device__ __half g_wph[MDIM * KDIM];     // w_proj fp16
__device__ __half g_wvh[MDIM * KDIM];     // (W_v * gamma) fp16
__device__ float  g_bias[MDIM];
__device__ float  g_s[NDIM];

// ---------------- helpers ----------------
__device__ __forceinline__ uint32_t smem_u32(const void* p) {
    uint32_t a;
    asm("{ .reg .u64 t; cvta.to.shared.u64 t, %1; cvt.u32.u64 %0, t; }" : "=r"(a) : "l"(p));
    return a;
}
__device__ __forceinline__ void cp_async16(uint32_t dst, const void* src) {
    asm volatile("cp.async.cg.shared.global [%0], [%1], 16;" :: "r"(dst), "l"(src) : "memory");
}
#define LDSM_X4(r0, r1, r2, r3, addr)                                         \
    asm volatile("ldmatrix.sync.aligned.m8n8.x4.shared.b16 {%0,%1,%2,%3}, [%4];" \
        : "=r"(r0), "=r"(r1), "=r"(r2), "=r"(r3) : "r"(addr))
#define LDSM_X4_T(r0, r1, r2, r3, addr)                                       \
    asm volatile("ldmatrix.sync.aligned.m8n8.x4.trans.shared.b16 {%0,%1,%2,%3}, [%4];" \
        : "=r"(r0), "=r"(r1), "=r"(r2), "=r"(r3) : "r"(addr))

__device__ __forceinline__ void mma_f16(float c[4], uint32_t a0, uint32_t a1, uint32_t a2, uint32_t a3,
                                        uint32_t b0, uint32_t b1) {
    asm volatile(
        "mma.sync.aligned.m16n8k16.row.col.f32.f16.f16.f32 "
        "{%0,%1,%2,%3}, {%4,%5,%6,%7}, {%8,%9}, {%0,%1,%2,%3};"
        : "+f"(c[0]), "+f"(c[1]), "+f"(c[2]), "+f"(c[3])
        : "r"(a0), "r"(a1), "r"(a2), "r"(a3), "r"(b0), "r"(b1));
}

// ---------------- kernel 1: prep (converts + bias, blockIdx-dispatched) ----------------
__global__ __launch_bounds__(256) void prep_kernel(
    const float* __restrict__ w_proj, const float* __restrict__ w_qkv,
    const float* __restrict__ gamma,  const float* __restrict__ b_qkv,
    const float* __restrict__ b_proj,
    __half* __restrict__ wph, __half* __restrict__ wvh, float* __restrict__ bias)
{
    const int bx  = blockIdx.x;
    const int tid = threadIdx.x;
    if (bx < 256) {
        const int i = (bx * 256 + tid) * 4;
        float4 v = *reinterpret_cast<const float4*>(w_proj + i);
        *reinterpret_cast<__half2*>(wph + i)     = __floats2half2_rn(v.x, v.y);
        *reinterpret_cast<__half2*>(wph + i + 2) = __floats2half2_rn(v.z, v.w);
    } else if (bx < 512) {
        const float* in = w_qkv + (size_t)1024 * KDIM;
        const int i = ((bx - 256) * 256 + tid) * 4;
        const int c = i & (KDIM - 1);
        float4 g = *reinterpret_cast<const float4*>(gamma + c);
        float4 v = *reinterpret_cast<const float4*>(in + i);
        *reinterpret_cast<__half2*>(wvh + i)     = __floats2half2_rn(v.x * g.x, v.y * g.y);
        *reinterpret_cast<__half2*>(wvh + i + 2) = __floats2half2_rn(v.z * g.z, v.w * g.w);
    } else {
        const int lane = tid & 31;
        const int o    = (bx - 512) * 8 + (tid >> 5);
        const float* wp = w_proj + (size_t)o * KDIM;
        const float* bq = b_qkv + 1024;
        float acc = 0.f;
        #pragma unroll
        for (int i = 0; i < 16; i++) {
            const int k = lane + 32 * i;
            acc = fmaf(wp[k], bq[k], acc);
        }
        #pragma unroll
        for (int off = 16; off > 0; off >>= 1)
            acc += __shfl_xor_sync(0xFFFFFFFFu, acc, off);
        if (lane == 0) bias[o] = acc + b_proj[o];
    }
}

// ---------------- kernel 2: scale (blocks 0..255) + fuse-weights mma (blocks 256..271) ----------------
__global__ __launch_bounds__(256, 2) void scale_fw_kernel(
    const float* __restrict__ x, float* __restrict__ s, __half* __restrict__ xh,
    const __half* __restrict__ Awp, const __half* __restrict__ Bwv,
    __half* __restrict__ Wf)
{
    extern __shared__ char smem[];
    const int tid = threadIdx.x;

    if (blockIdx.x < 256) {
        // ---- RMS scale + fp16 conversion, 128 tokens per block ----
        float2* red = reinterpret_cast<float2*>(smem);
        const int nl = tid & 63;
        const int q  = tid >> 6;
        const int n  = blockIdx.x * 128 + nl * 2;

        const float2* p = reinterpret_cast<const float2*>(x + (size_t)(q * 128) * NDIM + n);
        __half2* ph = reinterpret_cast<__half2*>(xh + (size_t)(q * 128) * NDIM + n);
        float ax = 0.f, ay = 0.f;
        #pragma unroll 8
        for (int c = 0; c < 128; c++) {
            float2 v = p[(size_t)c * (NDIM / 2)];
            ax = fmaf(v.x, v.x, ax);
            ay = fmaf(v.y, v.y, ay);
            ph[(size_t)c * (NDIM / 2)] = __floats2half2_rn(v.x, v.y);
        }
        red[tid] = make_float2(ax, ay);
        __syncthreads();
        if (tid < 64) {
            float2 a = red[tid], b = red[tid + 64], c2 = red[tid + 128], d = red[tid + 192];
            float tx2 = a.x + b.x + c2.x + d.x;
            float ty2 = a.y + b.y + c2.y + d.y;
            float2 sv;
            sv.x = SQRT_C / fmaxf(sqrtf(tx2), 1e-12f);
            sv.y = SQRT_C / fmaxf(sqrtf(ty2), 1e-12f);
            *reinterpret_cast<float2*>(s + blockIdx.x * 128 + tid * 2) = sv;
        }
        return;
    }

    // ---- fuse-weights GEMM: Wf = wph @ wvh  (B stride 512, 128x128 tiles) ----
    const uint32_t sbase = smem_u32(smem);
    const int bxx  = blockIdx.x - 256;
    const int lane = tid & 31;
    const int wid  = tid >> 5;
    const int wm   = wid >> 2;
    const int wn   = wid & 3;
    const int ty   = lane >> 2;
    const int tx   = lane & 3;
    const int m0   = (bxx >> 2) * 128;
    const int n0   = (bxx & 3) * 128;

    const int a_row = tid >> 1;
    const int a_sp  = (tid & 1) * 2;
    const int b_row = tid >> 3;
    const int b_sp  = (tid & 7) * 2;
    const __half* a_src = Awp + (size_t)(m0 + a_row) * KDIM + a_sp * 8;
    const __half* b_src = Bwv + (size_t)b_row * 512 + n0 + b_sp * 8;

    float c[4][4][4] = {};

    auto issue = [&](int ck) {
        const uint32_t ab = sbase + (uint32_t)(ck % 5) * FW_STAGE_B;
        const uint32_t bb = ab + FW_A_BYTES;
        const int k0 = ck * FW_BK;
        #pragma unroll
        for (int ss = 0; ss < 2; ss++)
            cp_async16(ab + (uint32_t)(a_row * 80 + (a_sp + ss) * 16), a_src + k0 + ss * 8);
        #pragma unroll
        for (int ss = 0; ss < 2; ss++)
            cp_async16(bb + (uint32_t)(b_row * 272 + (b_sp + ss) * 16),
                       b_src + (size_t)k0 * 512 + ss * 8);
        asm volatile("cp.async.commit_group;" ::: "memory");
    };

    issue(0); issue(1); issue(2); issue(3);

    const uint32_t a_lm = (uint32_t)(((wm * 64 + (lane & 15)) * FW_AROW_H + (lane >> 4) * 8) * 2);
    const uint32_t b_lm = (uint32_t)(FW_A_BYTES + (((lane & 15)) * FW_BROW_H + wn * 32 + (lane >> 4) * 8) * 2);

    #pragma unroll 1
    for (int it = 0; it < FW_NITER; ++it) {
        if (it + 3 < FW_NITER)      asm volatile("cp.async.wait_group 3;" ::: "memory");
        else if (it + 2 < FW_NITER) asm volatile("cp.async.wait_group 2;" ::: "memory");
        else if (it + 1 < FW_NITER) asm volatile("cp.async.wait_group 1;" ::: "memory");
        else                        asm volatile("cp.async.wait_group 0;" ::: "memory");
        __syncthreads();
        if (it + 4 < FW_NITER) issue(it + 4);

        const uint32_t stb = sbase + (uint32_t)(it % 5) * FW_STAGE_B;
        #pragma unroll
        for (int kk = 0; kk < 2; kk++) {
            uint32_t a[4][4];
            #pragma unroll
            for (int mt = 0; mt < 4; mt++)
                LDSM_X4(a[mt][0], a[mt][1], a[mt][2], a[mt][3],
                        stb + a_lm + mt * (16 * FW_AROW_H * 2) + kk * 32);
            uint32_t b[4][2];
            #pragma unroll
            for (int ntp = 0; ntp < 2; ntp++)
                LDSM_X4_T(b[ntp * 2][0], b[ntp * 2][1], b[ntp * 2 + 1][0], b[ntp * 2 + 1][1],
                          stb + b_lm + kk * (16 * FW_BROW_H * 2) + ntp * 32);
            #pragma unroll
            for (int mt = 0; mt < 4; mt++)
                #pragma unroll
                for (int nt = 0; nt < 4; nt++)
                    mma_f16(c[mt][nt], a[mt][0], a[mt][1], a[mt][2], a[mt][3],
                            b[nt][0], b[nt][1]);
        }
    }

    #pragma unroll
    for (int mt = 0; mt < 4; mt++)
        #pragma unroll
        for (int h = 0; h < 2; h++) {
            const int m = m0 + wm * 64 + mt * 16 + ty + h * 8;
            #pragma unroll
            for (int nt = 0; nt < 4; nt++) {
                const int nc = wn * 32 + nt * 8 + 2 * tx;
                *reinterpret_cast<__half2*>(Wf + (size_t)m * KDIM + n0 + nc) =
                    __floats2half2_rn(c[mt][nt][h * 2 + 0], c[mt][nt][h * 2 + 1]);
            }
        }
}

// ================= kernel 3: main GEMM (128x128, BK=64, 3 stages) =================
// 8 iterations: half the barriers of BK=32; 64 MMAs per compute phase.
__global__ __launch_bounds__(256, 2) void main_gemm_kernel(
    const __half* __restrict__ A,    // Wf [512,512] fp16
    const __half* __restrict__ Bh,   // x_h [512,32768] fp16 (operand + residual)
    const float* __restrict__ s,
    const float* __restrict__ bias,
    float* __restrict__ C)
{
    extern __shared__ char smem[];
    const uint32_t sbase = smem_u32(smem);
    const int tid  = threadIdx.x;
    const int lane = tid & 31;
    const int wid  = tid >> 5;
    const int wm   = wid >> 2;          // 0..1
    const int wn   = wid & 3;           // 0..3
    const int ty   = lane >> 2;
    const int tx   = lane & 3;
    const int m0   = blockIdx.x * BM;   // 4 m-tiles, fastest (L2 reuse of xh)
    const int n0   = blockIdx.y * BN;   // 256 n-tiles

    // loaders (per chunk: A 128 rows x 128B = 1024 segs; B 64 rows x 256B = 1024 segs; 4+4/thread)
    const int a_row = tid >> 1;          // 0..127
    const int a_sp  = (tid & 1) * 4;     // segs a_sp..a_sp+3
    const int b_row = tid >> 2;          // 0..63
    const int b_sp  = (tid & 3) * 4;     // segs b_sp..b_sp+3
    const __half* a_src = A + (size_t)(m0 + a_row) * KDIM + a_sp * 8;
    const __half* b_src = Bh + (size_t)b_row * NDIM + n0 + b_sp * 8;

    float c[4][4][4] = {};

    auto issue = [&](int ck) {
        const uint32_t ab = sbase + (uint32_t)(ck % STAGES) * STAGE_B;
        const uint32_t bb = ab + A_BYTES;
        const int k0 = ck * BK;
        #pragma unroll
        for (int ss = 0; ss < 4; ss++)
            cp_async16(ab + (uint32_t)(a_row * 144 + (a_sp + ss) * 16), a_src + k0 + ss * 8);
        #pragma unroll
        for (int ss = 0; ss < 4; ss++)
            cp_async16(bb + (uint32_t)(b_row * 272 + (b_sp + ss) * 16),
                       b_src + (size_t)k0 * NDIM + ss * 8);
        asm volatile("cp.async.commit_group;" ::: "memory");
    };

    issue(0); issue(1);

    const uint32_t a_lm = (uint32_t)(((wm * 64 + (lane & 15)) * AROW_H + (lane >> 4) * 8) * 2);
    const uint32_t b_lm = (uint32_t)(A_BYTES + (((lane & 15)) * BROW_H + wn * 32 + (lane >> 4) * 8) * 2);

    #pragma unroll 1
    for (int it = 0; it < NITER; ++it) {
        if (it + 1 < NITER) asm volatile("cp.async.wait_group 1;" ::: "memory");
        else                asm volatile("cp.async.wait_group 0;" ::: "memory");
        __syncthreads();
        if (it + 2 < NITER) issue(it + 2);

        const uint32_t stb = sbase + (uint32_t)(it % STAGES) * STAGE_B;
        #pragma unroll
        for (int kk = 0; kk < 4; kk++) {
            uint32_t a[4][4];
            #pragma unroll
            for (int mt = 0; mt < 4; mt++)
                LDSM_X4(a[mt][0], a[mt][1], a[mt][2], a[mt][3],
                        stb + a_lm + mt * (16 * AROW_H * 2) + kk * 32);
            uint32_t b[4][2];
            #pragma unroll
            for (int ntp = 0; ntp < 2; ntp++)
                LDSM_X4_T(b[ntp * 2][0], b[ntp * 2][1], b[ntp * 2 + 1][0], b[ntp * 2 + 1][1],
                          stb + b_lm + kk * (16 * BROW_H * 2) + ntp * 32);
            #pragma unroll
            for (int mt = 0; mt < 4; mt++)
                #pragma unroll
                for (int nt = 0; nt < 4; nt++)
                    mma_f16(c[mt][nt], a[mt][0], a[mt][1], a[mt][2], a[mt][3],
                            b[nt][0], b[nt][1]);
        }
    }

    // ---- epilogue: out = D*s[n] + bias[m] + xh[m][n] ----
    #pragma unroll
    for (int mt = 0; mt < 4; mt++) {
        #pragma unroll
        for (int h = 0; h < 2; h++) {
            const int m = m0 + wm * 64 + mt * 16 + ty + h * 8;
            const float bm = bias[m];
            const __half2* xrow = reinterpret_cast<const __half2*>(Bh + (size_t)m * NDIM + n0);
            float* crow = C + (size_t)m * NDIM + n0;
            #pragma unroll
            for (int nt = 0; nt < 4; nt++) {
                const int nc = wn * 32 + nt * 8 + 2 * tx;
                float2 xv = __half22float2(xrow[nc >> 1]);
                float2 sv = *reinterpret_cast<const float2*>(s + n0 + nc);
                float2 ov;
                ov.x = fmaf(c[mt][nt][h * 2 + 0], sv.x, bm + xv.x);
                ov.y = fmaf(c[mt][nt][h * 2 + 1], sv.y, bm + xv.y);
                *reinterpret_cast<float2*>(crow + nc) = ov;
            }
        }
    }
}

// ---------------- launcher ----------------
extern "C" void kernel_launch(void* const* d_in, const int* in_sizes, int n_in,
                              void* d_out, int out_size)
{
    const float* x      = (const float*)d_in[0];
    const float* gamma  = (const float*)d_in[1];
    const float* w_qkv  = (const float*)d_in[2];
    const float* b_qkv  = (const float*)d_in[3];
    const float* w_proj = (const float*)d_in[4];
    const float* b_proj = (const float*)d_in[5];
    float* out = (float*)d_out;

    __half *Wf, *xh, *wph, *wvh;
    float *bias, *s;
    cudaGetSymbolAddress((void**)&Wf,   g_Wf);
    cudaGetSymbolAddress((void**)&xh,   g_xh);
    cudaGetSymbolAddress((void**)&wph,  g_wph);
    cudaGetSymbolAddress((void**)&wvh,  g_wvh);
    cudaGetSymbolAddress((void**)&bias, g_bias);
    cudaGetSymbolAddress((void**)&s,    g_s);

    cudaFuncSetAttribute(scale_fw_kernel,
                         cudaFuncAttributeMaxDynamicSharedMemorySize, FW_SMEM);
    cudaFuncSetAttribute(main_gemm_kernel,
                         cudaFuncAttributeMaxDynamicSharedMemorySize, SMEM_TOTAL);

    prep_kernel<<<576, 256>>>(w_proj, w_qkv, gamma, b_qkv, b_proj, wph, wvh, bias);
    scale_fw_kernel<<<272, 256, FW_SMEM>>>(x, s, xh, wph, wvh, Wf);

    dim3 grid(MDIM / BM, NDIM / BN);   // (4, 256): m fastest
    main_gemm_kernel<<<grid, 256, SMEM_TOTAL>>>(Wf, xh, s, bias, out);
}